// round 1
// baseline (speedup 1.0000x reference)
#include <cuda_runtime.h>

#define HDIM 128
#define NMAX 50048
#define EMAX 800256

// Scratch (static __device__ arrays: allocation-free per harness rules)
__device__ float g_Qn[NMAX * HDIM];
__device__ float g_Kn[NMAX * HDIM];
__device__ float g_Vn[NMAX * HDIM];
__device__ int   g_cnt[NMAX + 1];
__device__ int   g_off[NMAX + 1];
__device__ int   g_wptr[NMAX];
__device__ int   g_csr[EMAX];

// ---------------------------------------------------------------------------
// CSR construction: zero counts -> histogram -> single-block scan -> scatter
// ---------------------------------------------------------------------------
__global__ void zero_cnt_kernel(int n) {
    int i = blockIdx.x * blockDim.x + threadIdx.x;
    if (i <= n) g_cnt[i] = 0;
}

__global__ void hist_kernel(const int* __restrict__ qidx, int E) {
    int i = blockIdx.x * blockDim.x + threadIdx.x;
    if (i < E) atomicAdd(&g_cnt[qidx[i]], 1);
}

// Exclusive prefix sum over g_cnt[0..n) -> g_off[0..n], g_wptr copy.
// Single block of 1024 threads, chunked.
__global__ void scan_kernel(int n) {
    __shared__ int wsum[32];
    __shared__ int carry_s;
    int tid = threadIdx.x, lane = tid & 31, wid = tid >> 5;
    if (tid == 0) carry_s = 0;
    __syncthreads();
    for (int base = 0; base < n; base += 1024) {
        int i = base + tid;
        int v0 = (i < n) ? g_cnt[i] : 0;
        int v = v0;
        #pragma unroll
        for (int d = 1; d < 32; d <<= 1) {
            int t = __shfl_up_sync(0xffffffffu, v, d);
            if (lane >= d) v += t;
        }
        if (lane == 31) wsum[wid] = v;
        __syncthreads();
        if (wid == 0) {
            int w = wsum[lane];
            #pragma unroll
            for (int d = 1; d < 32; d <<= 1) {
                int t = __shfl_up_sync(0xffffffffu, w, d);
                if (lane >= d) w += t;
            }
            wsum[lane] = w;
        }
        __syncthreads();
        int add = carry_s + (wid ? wsum[wid - 1] : 0);
        int excl = add + v - v0;
        if (i < n) { g_off[i] = excl; g_wptr[i] = excl; }
        __syncthreads();
        if (tid == 0) carry_s += wsum[31];
        __syncthreads();
    }
    if (threadIdx.x == 0) g_off[n] = carry_s;
}

__global__ void scatter_kernel(const int* __restrict__ qidx,
                               const int* __restrict__ kidx, int E) {
    int i = blockIdx.x * blockDim.x + threadIdx.x;
    if (i < E) {
        int d = qidx[i];
        int p = atomicAdd(&g_wptr[d], 1);
        g_csr[p] = kidx[i];
    }
}

// ---------------------------------------------------------------------------
// Fused per-node projection: Y = X @ W^T + b  for (q,Wq,bq)->Qn etc.
// Classic 128x128 tile SGEMM, K-chunks of 16, 8x8 register micro-tile.
// blockIdx.y selects which of the three projections.
// ---------------------------------------------------------------------------
__global__ __launch_bounds__(256, 2)
void proj_kernel(const float* __restrict__ q, const float* __restrict__ k,
                 const float* __restrict__ v,
                 const float* __restrict__ Wq, const float* __restrict__ bq,
                 const float* __restrict__ Wk, const float* __restrict__ bk,
                 const float* __restrict__ Wv, const float* __restrict__ bv,
                 int M) {
    const float *X, *W, *B;
    float* Y;
    if (blockIdx.y == 0)      { X = q; W = Wq; B = bq; Y = g_Qn; }
    else if (blockIdx.y == 1) { X = k; W = Wk; B = bk; Y = g_Kn; }
    else                      { X = v; W = Wv; B = bv; Y = g_Vn; }

    __shared__ float As[16][HDIM + 4];
    __shared__ float Bs[16][HDIM + 4];

    int tid = threadIdx.x;            // 256 threads
    int tx = tid & 15;                // output-col group (8 cols each)
    int ty = tid >> 4;                // output-row group (8 rows each)
    int row0 = blockIdx.x * 128;

    float acc[8][8];
    #pragma unroll
    for (int i = 0; i < 8; i++)
        #pragma unroll
        for (int j = 0; j < 8; j++) acc[i][j] = 0.f;

    float bias[8];
    #pragma unroll
    for (int j = 0; j < 8; j++) bias[j] = B[tx * 8 + j];

    for (int k0 = 0; k0 < HDIM; k0 += 16) {
        // Load A tile (128 rows x 16 k) and B tile (Bs[kk][j] = W[j][k0+kk])
        #pragma unroll
        for (int it = 0; it < 2; ++it) {
            int r  = (tid >> 2) + it * 64;   // 0..127
            int kk = (tid & 3) * 4;          // 0,4,8,12
            float4 a = make_float4(0.f, 0.f, 0.f, 0.f);
            int gr = row0 + r;
            if (gr < M) a = *(const float4*)(X + gr * HDIM + k0 + kk);
            As[kk + 0][r] = a.x; As[kk + 1][r] = a.y;
            As[kk + 2][r] = a.z; As[kk + 3][r] = a.w;
            float4 w4 = *(const float4*)(W + r * HDIM + k0 + kk);
            Bs[kk + 0][r] = w4.x; Bs[kk + 1][r] = w4.y;
            Bs[kk + 2][r] = w4.z; Bs[kk + 3][r] = w4.w;
        }
        __syncthreads();
        #pragma unroll
        for (int kk = 0; kk < 16; kk++) {
            float ra[8], rb[8];
            #pragma unroll
            for (int i = 0; i < 8; i++) ra[i] = As[kk][ty * 8 + i];
            #pragma unroll
            for (int j = 0; j < 8; j++) rb[j] = Bs[kk][tx * 8 + j];
            #pragma unroll
            for (int i = 0; i < 8; i++)
                #pragma unroll
                for (int j = 0; j < 8; j++)
                    acc[i][j] += ra[i] * rb[j];
        }
        __syncthreads();
    }

    #pragma unroll
    for (int i = 0; i < 8; i++) {
        int gr = row0 + ty * 8 + i;
        if (gr < M) {
            float4 o0 = make_float4(acc[i][0] + bias[0], acc[i][1] + bias[1],
                                    acc[i][2] + bias[2], acc[i][3] + bias[3]);
            float4 o1 = make_float4(acc[i][4] + bias[4], acc[i][5] + bias[5],
                                    acc[i][6] + bias[6], acc[i][7] + bias[7]);
            *(float4*)(Y + gr * HDIM + tx * 8 + 0) = o0;
            *(float4*)(Y + gr * HDIM + tx * 8 + 4) = o1;
        }
    }
}

// ---------------------------------------------------------------------------
// Fused attention gather: one warp per destination node.
// Lane l owns float4 at dims [4l, 4l+4); head = l/4 (16 dims per head = 4 lanes).
// score = dot(Qh,Kh)/4 ; ctx = (sum ex*V) / (sum ex)  -- no atomics, no denom pass.
// ---------------------------------------------------------------------------
__global__ void attn_kernel(float* __restrict__ out, int n) {
    int warp_id = (blockIdx.x * blockDim.x + threadIdx.x) >> 5;
    if (warp_id >= n) return;
    int lane = threadIdx.x & 31;

    const float4* Q4 = (const float4*)g_Qn;
    const float4* K4 = (const float4*)g_Kn;
    const float4* V4 = (const float4*)g_Vn;

    float4 qv = Q4[warp_id * 32 + lane];
    // fold 1/sqrt(D) = 0.25 into q
    qv.x *= 0.25f; qv.y *= 0.25f; qv.z *= 0.25f; qv.w *= 0.25f;

    float4 acc = make_float4(0.f, 0.f, 0.f, 0.f);
    float den = 0.f;

    int beg = g_off[warp_id];
    int end = g_off[warp_id + 1];

    for (int j = beg; j < end; j += 32) {
        int idx = j + lane;
        int ki = (idx < end) ? g_csr[idx] : 0;
        int cnt = min(32, end - j);
        for (int t = 0; t < cnt; t++) {
            int kid = __shfl_sync(0xffffffffu, ki, t);
            float4 k4 = K4[kid * 32 + lane];
            float s = qv.x * k4.x + qv.y * k4.y + qv.z * k4.z + qv.w * k4.w;
            // reduce within 4-lane head group
            s += __shfl_xor_sync(0xffffffffu, s, 1);
            s += __shfl_xor_sync(0xffffffffu, s, 2);
            float ex = __expf(s);
            float4 v4 = V4[kid * 32 + lane];
            acc.x += ex * v4.x; acc.y += ex * v4.y;
            acc.z += ex * v4.z; acc.w += ex * v4.w;
            den += ex;          // identical across the 4 lanes of each head
        }
    }

    float inv = 1.0f / den;     // every node has >= 1 in-edge by construction
    float4 o = make_float4(acc.x * inv, acc.y * inv, acc.z * inv, acc.w * inv);
    ((float4*)out)[warp_id * 32 + lane] = o;
}

// ---------------------------------------------------------------------------
extern "C" void kernel_launch(void* const* d_in, const int* in_sizes, int n_in,
                              void* d_out, int out_size) {
    const float* q  = (const float*)d_in[0];
    const float* k  = (const float*)d_in[1];
    const float* v  = (const float*)d_in[2];
    const float* Wq = (const float*)d_in[3];
    const float* bq = (const float*)d_in[4];
    const float* Wk = (const float*)d_in[5];
    const float* bk = (const float*)d_in[6];
    const float* Wv = (const float*)d_in[7];
    const float* bv = (const float*)d_in[8];
    const int* qidx = (const int*)d_in[9];
    const int* kidx = (const int*)d_in[10];

    int n = in_sizes[0] / HDIM;   // 50000
    int E = in_sizes[9];          // 800000

    zero_cnt_kernel<<<(n + 256) / 256, 256>>>(n);
    hist_kernel<<<(E + 255) / 256, 256>>>(qidx, E);
    scan_kernel<<<1, 1024>>>(n);
    scatter_kernel<<<(E + 255) / 256, 256>>>(qidx, kidx, E);

    dim3 pg((n + 127) / 128, 3);
    proj_kernel<<<pg, 256>>>(q, k, v, Wq, bq, Wk, bk, Wv, bv, n);

    attn_kernel<<<((long)n * 32 + 255) / 256, 256>>>((float*)d_out, n);
}

// round 2
// speedup vs baseline: 1.4335x; 1.4335x over previous
#include <cuda_runtime.h>
#include <cuda_fp16.h>

#define HDIM 128
#define NMAX 50048
#define EMAX 800256

// Scratch (static __device__ arrays: allocation-free per harness rules)
__device__ float  g_Qn[NMAX * HDIM];
__device__ __half g_Kh[NMAX * HDIM];
__device__ float  g_Vn[NMAX * HDIM];
__device__ int    g_cnt[NMAX + 1];
__device__ int    g_off[NMAX + 1];
__device__ int    g_wptr[NMAX];
__device__ int    g_csr[EMAX];

// ---------------------------------------------------------------------------
// CSR construction
// ---------------------------------------------------------------------------
__global__ void zero_cnt_kernel(int n) {
    int i = blockIdx.x * blockDim.x + threadIdx.x;
    if (i <= n) g_cnt[i] = 0;
}

__global__ void hist_kernel(const int* __restrict__ qidx, int E) {
    int i = blockIdx.x * blockDim.x + threadIdx.x;
    if (i < E) atomicAdd(&g_cnt[qidx[i]], 1);
}

__global__ void scan_kernel(int n) {
    __shared__ int wsum[32];
    __shared__ int carry_s;
    int tid = threadIdx.x, lane = tid & 31, wid = tid >> 5;
    if (tid == 0) carry_s = 0;
    __syncthreads();
    for (int base = 0; base < n; base += 1024) {
        int i = base + tid;
        int v0 = (i < n) ? g_cnt[i] : 0;
        int v = v0;
        #pragma unroll
        for (int d = 1; d < 32; d <<= 1) {
            int t = __shfl_up_sync(0xffffffffu, v, d);
            if (lane >= d) v += t;
        }
        if (lane == 31) wsum[wid] = v;
        __syncthreads();
        if (wid == 0) {
            int w = wsum[lane];
            #pragma unroll
            for (int d = 1; d < 32; d <<= 1) {
                int t = __shfl_up_sync(0xffffffffu, w, d);
                if (lane >= d) w += t;
            }
            wsum[lane] = w;
        }
        __syncthreads();
        int add = carry_s + (wid ? wsum[wid - 1] : 0);
        int excl = add + v - v0;
        if (i < n) { g_off[i] = excl; g_wptr[i] = excl; }
        __syncthreads();
        if (tid == 0) carry_s += wsum[31];
        __syncthreads();
    }
    if (threadIdx.x == 0) g_off[n] = carry_s;
}

__global__ void scatter_kernel(const int* __restrict__ qidx,
                               const int* __restrict__ kidx, int E) {
    int i = blockIdx.x * blockDim.x + threadIdx.x;
    if (i < E) {
        int d = qidx[i];
        int p = atomicAdd(&g_wptr[d], 1);
        g_csr[p] = kidx[i];
    }
}

// ---------------------------------------------------------------------------
// tf32 tensor-core projection: Y = X @ W^T + b  (blockIdx.y selects q/k/v).
// Block tile 128x128, 8 warps of 16 rows x 128 cols, mma.m16n8k8.tf32.
// ---------------------------------------------------------------------------
__device__ __forceinline__ unsigned f2tf32(float f) {
    unsigned r;
    asm("cvt.rna.tf32.f32 %0, %1;" : "=r"(r) : "f"(f));
    return r;
}

#define KS 36   // smem k-stride (padding for conflict-free frag loads)

__global__ __launch_bounds__(256, 2)
void proj_tc_kernel(const float* __restrict__ q, const float* __restrict__ k,
                    const float* __restrict__ v,
                    const float* __restrict__ Wq, const float* __restrict__ bq,
                    const float* __restrict__ Wk, const float* __restrict__ bk,
                    const float* __restrict__ Wv, const float* __restrict__ bv,
                    int M) {
    const float *X, *W, *B;
    int proj = blockIdx.y;
    if (proj == 0)      { X = q; W = Wq; B = bq; }
    else if (proj == 1) { X = k; W = Wk; B = bk; }
    else                { X = v; W = Wv; B = bv; }

    __shared__ unsigned As[128 * KS];
    __shared__ unsigned Bs[128 * KS];

    int tid  = threadIdx.x;
    int lane = tid & 31;
    int warp = tid >> 5;
    int t4g  = lane >> 2;   // groupID   (0..7)
    int tig  = lane & 3;    // thread in group (0..3)
    int mb   = warp * 16;   // warp's m-tile base within block
    int row0 = blockIdx.x * 128;

    float acc[16][4];
    #pragma unroll
    for (int nt = 0; nt < 16; nt++)
        #pragma unroll
        for (int c = 0; c < 4; c++) acc[nt][c] = 0.f;

    for (int kc = 0; kc < 4; kc++) {        // K chunks of 32
        // stage A (X rows) and B (W rows) chunks, tf32-converted
        #pragma unroll
        for (int it = 0; it < 4; it++) {
            int r  = it * 32 + (tid >> 3);
            int kk = (tid & 7) * 4;
            int gr = row0 + r;
            float4 a = make_float4(0.f, 0.f, 0.f, 0.f);
            if (gr < M) a = *(const float4*)(X + (long)gr * HDIM + kc * 32 + kk);
            uint4 at = make_uint4(f2tf32(a.x), f2tf32(a.y), f2tf32(a.z), f2tf32(a.w));
            *(uint4*)(As + r * KS + kk) = at;
            float4 w4 = *(const float4*)(W + (long)r * HDIM + kc * 32 + kk);
            uint4 wt = make_uint4(f2tf32(w4.x), f2tf32(w4.y), f2tf32(w4.z), f2tf32(w4.w));
            *(uint4*)(Bs + r * KS + kk) = wt;
        }
        __syncthreads();

        #pragma unroll
        for (int ks = 0; ks < 4; ks++) {
            int kt = ks * 8;
            unsigned a0 = As[(mb + t4g) * KS + kt + tig];
            unsigned a1 = As[(mb + t4g + 8) * KS + kt + tig];
            unsigned a2 = As[(mb + t4g) * KS + kt + tig + 4];
            unsigned a3 = As[(mb + t4g + 8) * KS + kt + tig + 4];
            #pragma unroll
            for (int nt = 0; nt < 16; nt++) {
                unsigned b0 = Bs[(nt * 8 + t4g) * KS + kt + tig];
                unsigned b1 = Bs[(nt * 8 + t4g) * KS + kt + tig + 4];
                asm volatile(
                    "mma.sync.aligned.m16n8k8.row.col.f32.tf32.tf32.f32 "
                    "{%0,%1,%2,%3},{%4,%5,%6,%7},{%8,%9},{%0,%1,%2,%3};"
                    : "+f"(acc[nt][0]), "+f"(acc[nt][1]),
                      "+f"(acc[nt][2]), "+f"(acc[nt][3])
                    : "r"(a0), "r"(a1), "r"(a2), "r"(a3), "r"(b0), "r"(b1));
            }
        }
        __syncthreads();
    }

    // epilogue: c0/c1 -> (row, col0), (row, col0+1); c2/c3 -> row+8
    int r0 = row0 + mb + t4g;
    int r1 = r0 + 8;
    #pragma unroll
    for (int nt = 0; nt < 16; nt++) {
        int col = nt * 8 + tig * 2;
        float bv0 = __ldg(B + col);
        float bv1 = __ldg(B + col + 1);
        float o00 = acc[nt][0] + bv0, o01 = acc[nt][1] + bv1;
        float o10 = acc[nt][2] + bv0, o11 = acc[nt][3] + bv1;
        if (proj == 0) {
            if (r0 < M) *(float2*)(g_Qn + (long)r0 * HDIM + col) = make_float2(o00, o01);
            if (r1 < M) *(float2*)(g_Qn + (long)r1 * HDIM + col) = make_float2(o10, o11);
        } else if (proj == 1) {
            if (r0 < M) *(__half2*)(g_Kh + (long)r0 * HDIM + col) = __floats2half2_rn(o00, o01);
            if (r1 < M) *(__half2*)(g_Kh + (long)r1 * HDIM + col) = __floats2half2_rn(o10, o11);
        } else {
            if (r0 < M) *(float2*)(g_Vn + (long)r0 * HDIM + col) = make_float2(o00, o01);
            if (r1 < M) *(float2*)(g_Vn + (long)r1 * HDIM + col) = make_float2(o10, o11);
        }
    }
}

// ---------------------------------------------------------------------------
// Fused attention gather: one warp per destination node.
// Lane l owns dims [4l, 4l+4); head = l/4. K is fp16, V fp32.
// ---------------------------------------------------------------------------
__device__ __forceinline__ void edge_step(int kid, int lane, const float4 qv,
                                          float4& acc, float& den) {
    const float4* V4 = (const float4*)g_Vn;
    uint2 kh = *(const uint2*)(g_Kh + (long)kid * HDIM + lane * 4);
    float2 k01 = __half22float2(*(__half2*)&kh.x);
    float2 k23 = __half22float2(*(__half2*)&kh.y);
    float s = qv.x * k01.x + qv.y * k01.y + qv.z * k23.x + qv.w * k23.y;
    s += __shfl_xor_sync(0xffffffffu, s, 1);
    s += __shfl_xor_sync(0xffffffffu, s, 2);
    float ex = __expf(s);
    float4 v4 = V4[(long)kid * 32 + lane];
    acc.x += ex * v4.x; acc.y += ex * v4.y;
    acc.z += ex * v4.z; acc.w += ex * v4.w;
    den += ex;
}

__global__ void attn_kernel(float* __restrict__ out, int n) {
    int warp_id = (blockIdx.x * blockDim.x + threadIdx.x) >> 5;
    if (warp_id >= n) return;
    int lane = threadIdx.x & 31;

    float4 qv = ((const float4*)g_Qn)[(long)warp_id * 32 + lane];
    qv.x *= 0.25f; qv.y *= 0.25f; qv.z *= 0.25f; qv.w *= 0.25f;

    float4 acc = make_float4(0.f, 0.f, 0.f, 0.f);
    float den = 0.f;

    int beg = g_off[warp_id];
    int end = g_off[warp_id + 1];

    for (int j = beg; j < end; j += 32) {
        int idx = j + lane;
        int ki = (idx < end) ? g_csr[idx] : 0;
        int cnt = min(32, end - j);
        int t = 0;
        for (; t + 4 <= cnt; t += 4) {
            int k0 = __shfl_sync(0xffffffffu, ki, t);
            int k1 = __shfl_sync(0xffffffffu, ki, t + 1);
            int k2 = __shfl_sync(0xffffffffu, ki, t + 2);
            int k3 = __shfl_sync(0xffffffffu, ki, t + 3);
            edge_step(k0, lane, qv, acc, den);
            edge_step(k1, lane, qv, acc, den);
            edge_step(k2, lane, qv, acc, den);
            edge_step(k3, lane, qv, acc, den);
        }
        for (; t < cnt; t++) {
            int kk = __shfl_sync(0xffffffffu, ki, t);
            edge_step(kk, lane, qv, acc, den);
        }
    }

    float inv = 1.0f / den;
    float4 o = make_float4(acc.x * inv, acc.y * inv, acc.z * inv, acc.w * inv);
    ((float4*)out)[(long)warp_id * 32 + lane] = o;
}

// ---------------------------------------------------------------------------
extern "C" void kernel_launch(void* const* d_in, const int* in_sizes, int n_in,
                              void* d_out, int out_size) {
    const float* q  = (const float*)d_in[0];
    const float* k  = (const float*)d_in[1];
    const float* v  = (const float*)d_in[2];
    const float* Wq = (const float*)d_in[3];
    const float* bq = (const float*)d_in[4];
    const float* Wk = (const float*)d_in[5];
    const float* bk = (const float*)d_in[6];
    const float* Wv = (const float*)d_in[7];
    const float* bv = (const float*)d_in[8];
    const int* qidx = (const int*)d_in[9];
    const int* kidx = (const int*)d_in[10];

    int n = in_sizes[0] / HDIM;   // 50000
    int E = in_sizes[9];          // 800000

    zero_cnt_kernel<<<(n + 256) / 256, 256>>>(n);
    hist_kernel<<<(E + 255) / 256, 256>>>(qidx, E);
    scan_kernel<<<1, 1024>>>(n);
    scatter_kernel<<<(E + 255) / 256, 256>>>(qidx, kidx, E);

    dim3 pg((n + 127) / 128, 3);
    proj_tc_kernel<<<pg, 256>>>(q, k, v, Wq, bq, Wk, bk, Wv, bv, n);

    attn_kernel<<<((long)n * 32 + 255) / 256, 256>>>((float*)d_out, n);
}

// round 3
// speedup vs baseline: 1.8137x; 1.2652x over previous
#include <cuda_runtime.h>
#include <cuda_fp16.h>

#define HDIM 128
#define NMAX 50048
#define EMAX 800256

// Scratch (static __device__ arrays: allocation-free per harness rules)
__device__ float  g_Qn[NMAX * HDIM];
__device__ __half g_KV[NMAX * 2 * HDIM];   // per node: [K half x128 | V half x128]
__device__ int    g_cnt[NMAX + 1];
__device__ int    g_off[NMAX + 1];
__device__ int    g_wptr[NMAX];
__device__ int    g_csr[EMAX];
__device__ int    g_bsum[64];

// ---------------------------------------------------------------------------
// CSR construction
// ---------------------------------------------------------------------------
__global__ void zero_cnt_kernel(int n) {
    int i = blockIdx.x * blockDim.x + threadIdx.x;
    if (i <= n) g_cnt[i] = 0;
}

__global__ void hist4_kernel(const int4* __restrict__ qidx4, int E4) {
    int i = blockIdx.x * blockDim.x + threadIdx.x;
    if (i < E4) {
        int4 q = qidx4[i];
        atomicAdd(&g_cnt[q.x], 1);
        atomicAdd(&g_cnt[q.y], 1);
        atomicAdd(&g_cnt[q.z], 1);
        atomicAdd(&g_cnt[q.w], 1);
    }
}

// Phase 1: per-1024-chunk exclusive scan (local), block totals -> g_bsum
__global__ void scan1_kernel(int n) {
    __shared__ int wsum[32];
    int tid = threadIdx.x, lane = tid & 31, wid = tid >> 5;
    int i = blockIdx.x * 1024 + tid;
    int v0 = (i < n) ? g_cnt[i] : 0;
    int v = v0;
    #pragma unroll
    for (int d = 1; d < 32; d <<= 1) {
        int t = __shfl_up_sync(0xffffffffu, v, d);
        if (lane >= d) v += t;
    }
    if (lane == 31) wsum[wid] = v;
    __syncthreads();
    if (wid == 0) {
        int w = wsum[lane];
        #pragma unroll
        for (int d = 1; d < 32; d <<= 1) {
            int t = __shfl_up_sync(0xffffffffu, w, d);
            if (lane >= d) w += t;
        }
        wsum[lane] = w;
    }
    __syncthreads();
    int excl = (wid ? wsum[wid - 1] : 0) + v - v0;
    if (i < n) g_off[i] = excl;
    if (tid == 1023) g_bsum[blockIdx.x] = excl + v0;
}

// Phase 2: exclusive scan of the (<=64) block sums; total -> g_off[n]
__global__ void scan2_kernel(int nb, int n) {
    __shared__ int ws[2];
    int tid = threadIdx.x;  // 64 threads
    int lane = tid & 31, wid = tid >> 5;
    int v0 = (tid < nb) ? g_bsum[tid] : 0;
    int v = v0;
    #pragma unroll
    for (int d = 1; d < 32; d <<= 1) {
        int t = __shfl_up_sync(0xffffffffu, v, d);
        if (lane >= d) v += t;
    }
    if (lane == 31) ws[wid] = v;
    __syncthreads();
    int incl = v + (wid == 1 ? ws[0] : 0);
    if (tid < nb) g_bsum[tid] = incl - v0;
    if (tid == nb - 1) g_off[n] = incl;
}

// Phase 3: add block base, duplicate to wptr
__global__ void scan3_kernel(int n) {
    int i = blockIdx.x * blockDim.x + threadIdx.x;
    if (i < n) {
        int o = g_off[i] + g_bsum[i >> 10];
        g_off[i] = o;
        g_wptr[i] = o;
    }
}

__global__ void scatter4_kernel(const int4* __restrict__ qidx4,
                                const int4* __restrict__ kidx4, int E4) {
    int i = blockIdx.x * blockDim.x + threadIdx.x;
    if (i < E4) {
        int4 q = qidx4[i];
        int4 k = kidx4[i];
        g_csr[atomicAdd(&g_wptr[q.x], 1)] = k.x;
        g_csr[atomicAdd(&g_wptr[q.y], 1)] = k.y;
        g_csr[atomicAdd(&g_wptr[q.z], 1)] = k.z;
        g_csr[atomicAdd(&g_wptr[q.w], 1)] = k.w;
    }
}

// ---------------------------------------------------------------------------
// tf32 tensor-core projection: Y = X @ W^T + b  (blockIdx.y selects q/k/v).
// ---------------------------------------------------------------------------
__device__ __forceinline__ unsigned f2tf32(float f) {
    unsigned r;
    asm("cvt.rna.tf32.f32 %0, %1;" : "=r"(r) : "f"(f));
    return r;
}

#define KS 36   // smem k-stride (padding for conflict-free frag loads)

__global__ __launch_bounds__(256, 2)
void proj_tc_kernel(const float* __restrict__ q, const float* __restrict__ k,
                    const float* __restrict__ v,
                    const float* __restrict__ Wq, const float* __restrict__ bq,
                    const float* __restrict__ Wk, const float* __restrict__ bk,
                    const float* __restrict__ Wv, const float* __restrict__ bv,
                    int M) {
    const float *X, *W, *B;
    int proj = blockIdx.y;
    if (proj == 0)      { X = q; W = Wq; B = bq; }
    else if (proj == 1) { X = k; W = Wk; B = bk; }
    else                { X = v; W = Wv; B = bv; }

    __shared__ unsigned As[128 * KS];
    __shared__ unsigned Bs[128 * KS];

    int tid  = threadIdx.x;
    int lane = tid & 31;
    int warp = tid >> 5;
    int t4g  = lane >> 2;
    int tig  = lane & 3;
    int mb   = warp * 16;
    int row0 = blockIdx.x * 128;

    float acc[16][4];
    #pragma unroll
    for (int nt = 0; nt < 16; nt++)
        #pragma unroll
        for (int c = 0; c < 4; c++) acc[nt][c] = 0.f;

    for (int kc = 0; kc < 4; kc++) {
        #pragma unroll
        for (int it = 0; it < 4; it++) {
            int r  = it * 32 + (tid >> 3);
            int kk = (tid & 7) * 4;
            int gr = row0 + r;
            float4 a = make_float4(0.f, 0.f, 0.f, 0.f);
            if (gr < M) a = *(const float4*)(X + (long)gr * HDIM + kc * 32 + kk);
            uint4 at = make_uint4(f2tf32(a.x), f2tf32(a.y), f2tf32(a.z), f2tf32(a.w));
            *(uint4*)(As + r * KS + kk) = at;
            float4 w4 = *(const float4*)(W + (long)r * HDIM + kc * 32 + kk);
            uint4 wt = make_uint4(f2tf32(w4.x), f2tf32(w4.y), f2tf32(w4.z), f2tf32(w4.w));
            *(uint4*)(Bs + r * KS + kk) = wt;
        }
        __syncthreads();

        #pragma unroll
        for (int ks = 0; ks < 4; ks++) {
            int kt = ks * 8;
            unsigned a0 = As[(mb + t4g) * KS + kt + tig];
            unsigned a1 = As[(mb + t4g + 8) * KS + kt + tig];
            unsigned a2 = As[(mb + t4g) * KS + kt + tig + 4];
            unsigned a3 = As[(mb + t4g + 8) * KS + kt + tig + 4];
            #pragma unroll
            for (int nt = 0; nt < 16; nt++) {
                unsigned b0 = Bs[(nt * 8 + t4g) * KS + kt + tig];
                unsigned b1 = Bs[(nt * 8 + t4g) * KS + kt + tig + 4];
                asm volatile(
                    "mma.sync.aligned.m16n8k8.row.col.f32.tf32.tf32.f32 "
                    "{%0,%1,%2,%3},{%4,%5,%6,%7},{%8,%9},{%0,%1,%2,%3};"
                    : "+f"(acc[nt][0]), "+f"(acc[nt][1]),
                      "+f"(acc[nt][2]), "+f"(acc[nt][3])
                    : "r"(a0), "r"(a1), "r"(a2), "r"(a3), "r"(b0), "r"(b1));
            }
        }
        __syncthreads();
    }

    int r0 = row0 + mb + t4g;
    int r1 = r0 + 8;
    #pragma unroll
    for (int nt = 0; nt < 16; nt++) {
        int col = nt * 8 + tig * 2;
        float bv0 = __ldg(B + col);
        float bv1 = __ldg(B + col + 1);
        float o00 = acc[nt][0] + bv0, o01 = acc[nt][1] + bv1;
        float o10 = acc[nt][2] + bv0, o11 = acc[nt][3] + bv1;
        if (proj == 0) {
            if (r0 < M) *(float2*)(g_Qn + (long)r0 * HDIM + col) = make_float2(o00, o01);
            if (r1 < M) *(float2*)(g_Qn + (long)r1 * HDIM + col) = make_float2(o10, o11);
        } else {
            // K at row offset 0, V at row offset HDIM within the packed KV row
            long base = (proj == 1) ? 0 : HDIM;
            if (r0 < M) *(__half2*)(g_KV + (long)r0 * 2 * HDIM + base + col) = __floats2half2_rn(o00, o01);
            if (r1 < M) *(__half2*)(g_KV + (long)r1 * 2 * HDIM + base + col) = __floats2half2_rn(o10, o11);
        }
    }
}

// ---------------------------------------------------------------------------
// Fused attention gather: one warp per destination node.
// Lane l owns dims [4l, 4l+4); head = l/4. K,V fp16 packed per node row.
// ---------------------------------------------------------------------------
__device__ __forceinline__ void edge_step(int kid, int lane, const float4 qv,
                                          float4& acc, float& den) {
    const __half* kv = g_KV + ((long)kid << 8);
    uint2 kh = *(const uint2*)(kv + (lane << 2));
    uint2 vh = *(const uint2*)(kv + HDIM + (lane << 2));
    float2 k01 = __half22float2(*(__half2*)&kh.x);
    float2 k23 = __half22float2(*(__half2*)&kh.y);
    float s = qv.x * k01.x + qv.y * k01.y + qv.z * k23.x + qv.w * k23.y;
    s += __shfl_xor_sync(0xffffffffu, s, 1);
    s += __shfl_xor_sync(0xffffffffu, s, 2);
    float ex = __expf(s);
    float2 v01 = __half22float2(*(__half2*)&vh.x);
    float2 v23 = __half22float2(*(__half2*)&vh.y);
    acc.x += ex * v01.x; acc.y += ex * v01.y;
    acc.z += ex * v23.x; acc.w += ex * v23.y;
    den += ex;
}

__global__ void attn_kernel(float* __restrict__ out, int n) {
    int warp_id = (blockIdx.x * blockDim.x + threadIdx.x) >> 5;
    if (warp_id >= n) return;
    int lane = threadIdx.x & 31;

    float4 qv = ((const float4*)g_Qn)[(long)warp_id * 32 + lane];
    qv.x *= 0.25f; qv.y *= 0.25f; qv.z *= 0.25f; qv.w *= 0.25f;

    float4 acc = make_float4(0.f, 0.f, 0.f, 0.f);
    float den = 0.f;

    int beg = g_off[warp_id];
    int end = g_off[warp_id + 1];

    for (int j = beg; j < end; j += 32) {
        int idx = j + lane;
        int ki = (idx < end) ? g_csr[idx] : 0;
        int cnt = min(32, end - j);
        int t = 0;
        for (; t + 4 <= cnt; t += 4) {
            int k0 = __shfl_sync(0xffffffffu, ki, t);
            int k1 = __shfl_sync(0xffffffffu, ki, t + 1);
            int k2 = __shfl_sync(0xffffffffu, ki, t + 2);
            int k3 = __shfl_sync(0xffffffffu, ki, t + 3);
            edge_step(k0, lane, qv, acc, den);
            edge_step(k1, lane, qv, acc, den);
            edge_step(k2, lane, qv, acc, den);
            edge_step(k3, lane, qv, acc, den);
        }
        for (; t < cnt; t++) {
            int kk = __shfl_sync(0xffffffffu, ki, t);
            edge_step(kk, lane, qv, acc, den);
        }
    }

    float inv = 1.0f / den;
    float4 o = make_float4(acc.x * inv, acc.y * inv, acc.z * inv, acc.w * inv);
    ((float4*)out)[(long)warp_id * 32 + lane] = o;
}

// ---------------------------------------------------------------------------
extern "C" void kernel_launch(void* const* d_in, const int* in_sizes, int n_in,
                              void* d_out, int out_size) {
    const float* q  = (const float*)d_in[0];
    const float* k  = (const float*)d_in[1];
    const float* v  = (const float*)d_in[2];
    const float* Wq = (const float*)d_in[3];
    const float* bq = (const float*)d_in[4];
    const float* Wk = (const float*)d_in[5];
    const float* bk = (const float*)d_in[6];
    const float* Wv = (const float*)d_in[7];
    const float* bv = (const float*)d_in[8];
    const int* qidx = (const int*)d_in[9];
    const int* kidx = (const int*)d_in[10];

    int n = in_sizes[0] / HDIM;   // 50000
    int E = in_sizes[9];          // 800000
    int E4 = E >> 2;              // E divisible by 4 (800000)
    int nblk = (n + 1023) / 1024; // scan chunks

    static cudaStream_t s2 = nullptr;
    static cudaEvent_t e_fork = nullptr, e_join = nullptr;
    if (!s2) {
        cudaStreamCreate(&s2);
        cudaEventCreateWithFlags(&e_fork, cudaEventDisableTiming);
        cudaEventCreateWithFlags(&e_join, cudaEventDisableTiming);
    }

    // Fork: projection on s2, CSR build on the main stream.
    cudaEventRecord(e_fork, 0);
    cudaStreamWaitEvent(s2, e_fork, 0);

    dim3 pg((n + 127) / 128, 3);
    proj_tc_kernel<<<pg, 256, 0, s2>>>(q, k, v, Wq, bq, Wk, bk, Wv, bv, n);

    zero_cnt_kernel<<<(n + 256) / 256, 256>>>(n);
    hist4_kernel<<<(E4 + 255) / 256, 256>>>((const int4*)qidx, E4);
    scan1_kernel<<<nblk, 1024>>>(n);
    scan2_kernel<<<1, 64>>>(nblk, n);
    scan3_kernel<<<(n + 255) / 256, 256>>>(n);
    scatter4_kernel<<<(E4 + 255) / 256, 256>>>((const int4*)qidx, (const int4*)kidx, E4);

    // Join, then attention.
    cudaEventRecord(e_join, s2);
    cudaStreamWaitEvent(0, e_join, 0);

    attn_kernel<<<((long)n * 32 + 255) / 256, 256>>>((float*)d_out, n);
}

// round 4
// speedup vs baseline: 1.9728x; 1.0877x over previous
#include <cuda_runtime.h>
#include <cuda_fp16.h>

#define HDIM 128
#define NMAX 50048
#define EMAX 800256

// Scratch (static __device__ arrays: allocation-free per harness rules)
__device__ float  g_Qn[NMAX * HDIM];
// Interleaved KV: per node 256 halves; lane l owns halves [8l, 8l+8):
//   [K(4l..4l+3), V(4l..4l+3)]  -> one 16B load per lane per edge.
__device__ __half g_KV[NMAX * 2 * HDIM];
__device__ int    g_cnt[NMAX + 1];
__device__ int    g_off[NMAX + 1];
__device__ int    g_wptr[NMAX];
__device__ int    g_csr[EMAX];
__device__ int    g_bsum[64];

// ---------------------------------------------------------------------------
// CSR construction
// ---------------------------------------------------------------------------
__global__ void zero_cnt_kernel(int n) {
    int i = blockIdx.x * blockDim.x + threadIdx.x;
    if (i <= n) g_cnt[i] = 0;
}

__global__ void hist4_kernel(const int4* __restrict__ qidx4, int E4) {
    int i = blockIdx.x * blockDim.x + threadIdx.x;
    if (i < E4) {
        int4 q = qidx4[i];
        atomicAdd(&g_cnt[q.x], 1);
        atomicAdd(&g_cnt[q.y], 1);
        atomicAdd(&g_cnt[q.z], 1);
        atomicAdd(&g_cnt[q.w], 1);
    }
}

// Phase 1: per-1024-chunk exclusive scan (local), block totals -> g_bsum
__global__ void scan1_kernel(int n) {
    __shared__ int wsum[32];
    int tid = threadIdx.x, lane = tid & 31, wid = tid >> 5;
    int i = blockIdx.x * 1024 + tid;
    int v0 = (i < n) ? g_cnt[i] : 0;
    int v = v0;
    #pragma unroll
    for (int d = 1; d < 32; d <<= 1) {
        int t = __shfl_up_sync(0xffffffffu, v, d);
        if (lane >= d) v += t;
    }
    if (lane == 31) wsum[wid] = v;
    __syncthreads();
    if (wid == 0) {
        int w = wsum[lane];
        #pragma unroll
        for (int d = 1; d < 32; d <<= 1) {
            int t = __shfl_up_sync(0xffffffffu, w, d);
            if (lane >= d) w += t;
        }
        wsum[lane] = w;
    }
    __syncthreads();
    int excl = (wid ? wsum[wid - 1] : 0) + v - v0;
    if (i < n) g_off[i] = excl;
    if (tid == 1023) g_bsum[blockIdx.x] = excl + v0;
}

// Phase 2: exclusive scan of the (<=64) block sums; total -> g_off[n]
__global__ void scan2_kernel(int nb, int n) {
    __shared__ int ws[2];
    int tid = threadIdx.x;  // 64 threads
    int lane = tid & 31, wid = tid >> 5;
    int v0 = (tid < nb) ? g_bsum[tid] : 0;
    int v = v0;
    #pragma unroll
    for (int d = 1; d < 32; d <<= 1) {
        int t = __shfl_up_sync(0xffffffffu, v, d);
        if (lane >= d) v += t;
    }
    if (lane == 31) ws[wid] = v;
    __syncthreads();
    int incl = v + (wid == 1 ? ws[0] : 0);
    if (tid < nb) g_bsum[tid] = incl - v0;
    if (tid == nb - 1) g_off[n] = incl;
}

// Phase 3: add block base, duplicate to wptr
__global__ void scan3_kernel(int n) {
    int i = blockIdx.x * blockDim.x + threadIdx.x;
    if (i < n) {
        int o = g_off[i] + g_bsum[i >> 10];
        g_off[i] = o;
        g_wptr[i] = o;
    }
}

__global__ void scatter4_kernel(const int4* __restrict__ qidx4,
                                const int4* __restrict__ kidx4, int E4) {
    int i = blockIdx.x * blockDim.x + threadIdx.x;
    if (i < E4) {
        int4 q = qidx4[i];
        int4 k = kidx4[i];
        g_csr[atomicAdd(&g_wptr[q.x], 1)] = k.x;
        g_csr[atomicAdd(&g_wptr[q.y], 1)] = k.y;
        g_csr[atomicAdd(&g_wptr[q.z], 1)] = k.z;
        g_csr[atomicAdd(&g_wptr[q.w], 1)] = k.w;
    }
}

// ---------------------------------------------------------------------------
// tf32 tensor-core projection: Y = X @ W^T + b  (blockIdx.y selects q/k/v).
// ---------------------------------------------------------------------------
__device__ __forceinline__ unsigned f2tf32(float f) {
    unsigned r;
    asm("cvt.rna.tf32.f32 %0, %1;" : "=r"(r) : "f"(f));
    return r;
}

#define KS 36   // smem k-stride (padding for conflict-free frag loads)

__global__ __launch_bounds__(256, 2)
void proj_tc_kernel(const float* __restrict__ q, const float* __restrict__ k,
                    const float* __restrict__ v,
                    const float* __restrict__ Wq, const float* __restrict__ bq,
                    const float* __restrict__ Wk, const float* __restrict__ bk,
                    const float* __restrict__ Wv, const float* __restrict__ bv,
                    int M) {
    const float *X, *W, *B;
    int proj = blockIdx.y;
    if (proj == 0)      { X = q; W = Wq; B = bq; }
    else if (proj == 1) { X = k; W = Wk; B = bk; }
    else                { X = v; W = Wv; B = bv; }

    __shared__ unsigned As[128 * KS];
    __shared__ unsigned Bs[128 * KS];

    int tid  = threadIdx.x;
    int lane = tid & 31;
    int warp = tid >> 5;
    int t4g  = lane >> 2;
    int tig  = lane & 3;
    int mb   = warp * 16;
    int row0 = blockIdx.x * 128;

    float acc[16][4];
    #pragma unroll
    for (int nt = 0; nt < 16; nt++)
        #pragma unroll
        for (int c = 0; c < 4; c++) acc[nt][c] = 0.f;

    for (int kc = 0; kc < 4; kc++) {
        #pragma unroll
        for (int it = 0; it < 4; it++) {
            int r  = it * 32 + (tid >> 3);
            int kk = (tid & 7) * 4;
            int gr = row0 + r;
            float4 a = make_float4(0.f, 0.f, 0.f, 0.f);
            if (gr < M) a = *(const float4*)(X + (long)gr * HDIM + kc * 32 + kk);
            uint4 at = make_uint4(f2tf32(a.x), f2tf32(a.y), f2tf32(a.z), f2tf32(a.w));
            *(uint4*)(As + r * KS + kk) = at;
            float4 w4 = *(const float4*)(W + (long)r * HDIM + kc * 32 + kk);
            uint4 wt = make_uint4(f2tf32(w4.x), f2tf32(w4.y), f2tf32(w4.z), f2tf32(w4.w));
            *(uint4*)(Bs + r * KS + kk) = wt;
        }
        __syncthreads();

        #pragma unroll
        for (int ks = 0; ks < 4; ks++) {
            int kt = ks * 8;
            unsigned a0 = As[(mb + t4g) * KS + kt + tig];
            unsigned a1 = As[(mb + t4g + 8) * KS + kt + tig];
            unsigned a2 = As[(mb + t4g) * KS + kt + tig + 4];
            unsigned a3 = As[(mb + t4g + 8) * KS + kt + tig + 4];
            #pragma unroll
            for (int nt = 0; nt < 16; nt++) {
                unsigned b0 = Bs[(nt * 8 + t4g) * KS + kt + tig];
                unsigned b1 = Bs[(nt * 8 + t4g) * KS + kt + tig + 4];
                asm volatile(
                    "mma.sync.aligned.m16n8k8.row.col.f32.tf32.tf32.f32 "
                    "{%0,%1,%2,%3},{%4,%5,%6,%7},{%8,%9},{%0,%1,%2,%3};"
                    : "+f"(acc[nt][0]), "+f"(acc[nt][1]),
                      "+f"(acc[nt][2]), "+f"(acc[nt][3])
                    : "r"(a0), "r"(a1), "r"(a2), "r"(a3), "r"(b0), "r"(b1));
            }
        }
        __syncthreads();
    }

    int r0 = row0 + mb + t4g;
    int r1 = r0 + 8;
    #pragma unroll
    for (int nt = 0; nt < 16; nt++) {
        int col = nt * 8 + tig * 2;   // even; col, col+1 in same 4-chunk
        float bv0 = __ldg(B + col);
        float bv1 = __ldg(B + col + 1);
        float o00 = acc[nt][0] + bv0, o01 = acc[nt][1] + bv1;
        float o10 = acc[nt][2] + bv0, o11 = acc[nt][3] + bv1;
        if (proj == 0) {
            if (r0 < M) *(float2*)(g_Qn + (long)r0 * HDIM + col) = make_float2(o00, o01);
            if (r1 < M) *(float2*)(g_Qn + (long)r1 * HDIM + col) = make_float2(o10, o11);
        } else {
            // Interleaved KV half-index: chunk = col>>2, within = col&3
            // K -> chunk*8 + within, V -> chunk*8 + 4 + within
            long hoff = ((long)(col >> 2)) * 8 + (col & 3) + ((proj == 1) ? 0 : 4);
            if (r0 < M) *(__half2*)(g_KV + (long)r0 * 2 * HDIM + hoff) = __floats2half2_rn(o00, o01);
            if (r1 < M) *(__half2*)(g_KV + (long)r1 * 2 * HDIM + hoff) = __floats2half2_rn(o10, o11);
        }
    }
}

// ---------------------------------------------------------------------------
// Fused attention gather: one warp per destination node.
// Lane l owns dims [4l, 4l+4); head = l/4. KV interleaved fp16:
// one LDG.128 per lane per edge.
// ---------------------------------------------------------------------------
__device__ __forceinline__ void edge_step(int kid, int lane, const float4 qv,
                                          float4& acc, float& den) {
    const uint4* kvp = (const uint4*)(g_KV + ((long)kid << 8));
    uint4 kvv = kvp[lane];
    float2 k01 = __half22float2(*(__half2*)&kvv.x);
    float2 k23 = __half22float2(*(__half2*)&kvv.y);
    float s = qv.x * k01.x + qv.y * k01.y + qv.z * k23.x + qv.w * k23.y;
    s += __shfl_xor_sync(0xffffffffu, s, 1);
    s += __shfl_xor_sync(0xffffffffu, s, 2);
    float ex = __expf(s);
    float2 v01 = __half22float2(*(__half2*)&kvv.z);
    float2 v23 = __half22float2(*(__half2*)&kvv.w);
    acc.x += ex * v01.x; acc.y += ex * v01.y;
    acc.z += ex * v23.x; acc.w += ex * v23.y;
    den += ex;
}

__global__ __launch_bounds__(256)
void attn_kernel(float* __restrict__ out, int n) {
    int warp_id = (blockIdx.x * blockDim.x + threadIdx.x) >> 5;
    if (warp_id >= n) return;
    int lane = threadIdx.x & 31;

    float4 qv = ((const float4*)g_Qn)[(long)warp_id * 32 + lane];
    qv.x *= 0.25f; qv.y *= 0.25f; qv.z *= 0.25f; qv.w *= 0.25f;

    float4 acc0 = make_float4(0.f, 0.f, 0.f, 0.f);
    float4 acc1 = make_float4(0.f, 0.f, 0.f, 0.f);
    float den0 = 0.f, den1 = 0.f;

    int beg = g_off[warp_id];
    int end = g_off[warp_id + 1];

    int j = beg;
    for (; j + 4 <= end; j += 4) {
        // uniform-address scalar loads: LSU broadcast, same 128B line
        int k0 = g_csr[j + 0];
        int k1 = g_csr[j + 1];
        int k2 = g_csr[j + 2];
        int k3 = g_csr[j + 3];
        edge_step(k0, lane, qv, acc0, den0);
        edge_step(k1, lane, qv, acc1, den1);
        edge_step(k2, lane, qv, acc0, den0);
        edge_step(k3, lane, qv, acc1, den1);
    }
    for (; j < end; j++) {
        int kk = g_csr[j];
        edge_step(kk, lane, qv, acc0, den0);
    }

    float den = den0 + den1;
    float inv = 1.0f / den;
    float4 o = make_float4((acc0.x + acc1.x) * inv, (acc0.y + acc1.y) * inv,
                           (acc0.z + acc1.z) * inv, (acc0.w + acc1.w) * inv);
    ((float4*)out)[(long)warp_id * 32 + lane] = o;
}

// ---------------------------------------------------------------------------
extern "C" void kernel_launch(void* const* d_in, const int* in_sizes, int n_in,
                              void* d_out, int out_size) {
    const float* q  = (const float*)d_in[0];
    const float* k  = (const float*)d_in[1];
    const float* v  = (const float*)d_in[2];
    const float* Wq = (const float*)d_in[3];
    const float* bq = (const float*)d_in[4];
    const float* Wk = (const float*)d_in[5];
    const float* bk = (const float*)d_in[6];
    const float* Wv = (const float*)d_in[7];
    const float* bv = (const float*)d_in[8];
    const int* qidx = (const int*)d_in[9];
    const int* kidx = (const int*)d_in[10];

    int n = in_sizes[0] / HDIM;   // 50000
    int E = in_sizes[9];          // 800000
    int E4 = E >> 2;
    int nblk = (n + 1023) / 1024;

    static cudaStream_t s2 = nullptr;
    static cudaEvent_t e_fork = nullptr, e_join = nullptr;
    if (!s2) {
        cudaStreamCreate(&s2);
        cudaEventCreateWithFlags(&e_fork, cudaEventDisableTiming);
        cudaEventCreateWithFlags(&e_join, cudaEventDisableTiming);
    }

    // Fork: projection on s2, CSR build on the main stream.
    cudaEventRecord(e_fork, 0);
    cudaStreamWaitEvent(s2, e_fork, 0);

    dim3 pg((n + 127) / 128, 3);
    proj_tc_kernel<<<pg, 256, 0, s2>>>(q, k, v, Wq, bq, Wk, bk, Wv, bv, n);

    zero_cnt_kernel<<<(n + 256) / 256, 256>>>(n);
    hist4_kernel<<<(E4 + 255) / 256, 256>>>((const int4*)qidx, E4);
    scan1_kernel<<<nblk, 1024>>>(n);
    scan2_kernel<<<1, 64>>>(nblk, n);
    scan3_kernel<<<(n + 255) / 256, 256>>>(n);
    scatter4_kernel<<<(E4 + 255) / 256, 256>>>((const int4*)qidx, (const int4*)kidx, E4);

    // Join, then attention.
    cudaEventRecord(e_join, s2);
    cudaStreamWaitEvent(0, e_join, 0);

    attn_kernel<<<((long)n * 32 + 255) / 256, 256>>>((float*)d_out, n);
}